// round 15
// baseline (speedup 1.0000x reference)
#include <cuda_runtime.h>
#include <cuda_bf16.h>
#include <math.h>
#include <stdint.h>

#define BTOT 32768
#define BCH 8192          // chunk size (4 chunks)
#define NDM 256
#define NDI 256
#define NDS 16
#define NFF 512

// ---- scratch (static device globals; no allocation) ----
__device__ float g_u[(size_t)BTOT*NDI];
__device__ float g_gate[(size_t)BTOT*NDI];
__device__ float g_delta[(size_t)BTOT*NDI];
__device__ float g_Bm[(size_t)BTOT*NDS];
__device__ float g_Cm[(size_t)BTOT*NDS];
__device__ float g_y[(size_t)BTOT*NDI];
__device__ float g_s[(size_t)BTOT*NDM];
__device__ float g_negA[NDI*NDS];

// packed split-bf16 activations: row = [hi(0..K-1) | lo(0..K-1)]
__device__ __nv_bfloat16 g_pospk[(size_t)BTOT*512];   // K=256
__device__ __nv_bfloat16 g_ypk[(size_t)BTOT*512];     // K=256
__device__ __nv_bfloat16 g_tpk[(size_t)BTOT*1024];    // K=512
// packed split-bf16 weights: row n = [hi(0..K-1) | lo(0..K-1)]
__device__ __nv_bfloat16 g_W0pk[512*512];
__device__ __nv_bfloat16 g_W1pk[512*512];
__device__ __nv_bfloat16 g_W2pk[256*1024];

__device__ __forceinline__ float siluf(float x) { return x / (1.f + __expf(-x)); }

__device__ __forceinline__ void packsplit(float v, __nv_bfloat16* hi_p, __nv_bfloat16* lo_p) {
    __nv_bfloat16 hi = __float2bfloat16(v);
    *hi_p = hi;
    *lo_p = __float2bfloat16(v - __bfloat162float(hi));
}

// ---------------- K0a: precompute -exp(A_log) ----------------
__global__ void k_prep(const float* __restrict__ A_log) {
    int i = blockIdx.x * 256 + threadIdx.x;
    g_negA[i] = -expf(A_log[i]);
}

// ---------------- K0b: pack weights to split bf16 ----------------
__global__ void k_packw(const float* __restrict__ W, int K, int sel) {
    int i = blockIdx.x * 256 + threadIdx.x;    // over rows*K
    int n = i / K, k = i - n * K;
    __nv_bfloat16* dst = sel == 0 ? g_W0pk : (sel == 1 ? g_W1pk : g_W2pk);
    float v = W[i];
    __nv_bfloat16 hi = __float2bfloat16(v);
    dst[(size_t)n * 2 * K + k] = hi;
    dst[(size_t)n * 2 * K + K + k] = __float2bfloat16(v - __bfloat162float(hi));
}

// ---------------- K1: sine embedding (writes packed bf16 split) ----------------
__global__ void __launch_bounds__(256) k_embed(const float* __restrict__ x0, int boff) {
    int b = boff + blockIdx.x;
    int c = threadIdx.x;
    int a = c >> 6;
    int w = c & 63;
    int j = w >> 1;
    float v = x0[b * 4 + a];
    float freq_inv = __expf(-(float)j * 0.28782313662425576f); // ln(10000)/32
    float p = v * 6.283185307179586f * freq_inv;
    float val = (w & 1) ? __cosf(p) : __sinf(p);
    packsplit(val, &g_pospk[(size_t)b * 512 + c], &g_pospk[(size_t)b * 512 + 256 + c]);
}

// ================= HMMA (mma.sync bf16) split-bf16 GEMM =================
// persistent CTAs + cp.async double buffering + cross-tile prefetch
__device__ __forceinline__ void ldsm_x4(uint32_t* a, uint32_t addr) {
    asm volatile("ldmatrix.sync.aligned.m8n8.x4.shared.b16 {%0,%1,%2,%3}, [%4];"
                 : "=r"(a[0]), "=r"(a[1]), "=r"(a[2]), "=r"(a[3]) : "r"(addr));
}
__device__ __forceinline__ void ldsm_x2(uint32_t* b, uint32_t addr) {
    asm volatile("ldmatrix.sync.aligned.m8n8.x2.shared.b16 {%0,%1}, [%2];"
                 : "=r"(b[0]), "=r"(b[1]) : "r"(addr));
}
__device__ __forceinline__ void mma16816(float* d, const uint32_t* a, const uint32_t* b) {
    asm volatile(
        "mma.sync.aligned.m16n8k16.row.col.f32.bf16.bf16.f32 "
        "{%0,%1,%2,%3}, {%4,%5,%6,%7}, {%8,%9}, {%0,%1,%2,%3};"
        : "+f"(d[0]), "+f"(d[1]), "+f"(d[2]), "+f"(d[3])
        : "r"(a[0]), "r"(a[1]), "r"(a[2]), "r"(a[3]), "r"(b[0]), "r"(b[1]));
}
__device__ __forceinline__ void cp16(uint32_t smem, const void* gmem) {
    asm volatile("cp.async.cg.shared.global [%0], [%1], 16;"
                 :: "r"(smem), "l"(gmem));
}
__device__ __forceinline__ void cp_commit() {
    asm volatile("cp.async.commit_group;");
}
template <int N>
__device__ __forceinline__ void cp_wait() {
    asm volatile("cp.async.wait_group %0;" :: "n"(N));
}

// MODE 0: A=g_pospk K=256, NOUT=512: n<256 -> g_u=silu(v), else g_gate=v
// MODE 1: A=g_ypk   K=256, NOUT=512: g_tpk = packsplit(relu(v + b1[n]))
// MODE 2: A=g_tpk   K=512, NOUT=256: g_s = v + b2[n] + g_y[m,n]
template <int KDIM, int NOUT, int MODE>
__global__ void __launch_bounds__(256) k_hgemm(const float* __restrict__ bias, int mbase) {
    extern __shared__ char smem_raw[];
    const __nv_bfloat16* __restrict__ Apk =
        MODE == 0 ? g_pospk : (MODE == 1 ? g_ypk : g_tpk);
    const __nv_bfloat16* __restrict__ Wpk =
        MODE == 0 ? g_W0pk : (MODE == 1 ? g_W1pk : g_W2pk);

    constexpr int KD2 = 2 * KDIM;
    constexpr int KCH = KDIM / 64;      // 64-col chunks per pass
    constexpr int NCH = 3 * KCH;        // total chunks over 3 passes (even)
    constexpr int STG = 32768;          // stage size: 16KB A + 16KB B
    constexpr int NX = NOUT / 128;      // tiles along N
    constexpr int NT = (BCH / 128) * NX;

    const int tid = threadIdx.x;
    const int wid = tid >> 5;
    const int lane = tid & 31;
    const int wm = wid & 1;
    const int wn = wid >> 1;
    uint32_t sb = (uint32_t)__cvta_generic_to_shared(smem_raw);
    sb = (sb + 127u) & ~127u;

    const int sr = tid >> 3;
    const int sc = tid & 7;
    const uint32_t soff = (uint32_t)(((sc ^ (sr & 7)) * 16));

    auto stage = [&](int tile, int c, int buf) {
        int m0 = mbase + (tile / NX) * 128;
        int n0 = (tile - (tile / NX) * NX) * 128;
        int pass = c / KCH;
        int kc = (c - pass * KCH) * 64;
        int acol = (pass == 2 ? KDIM : 0) + kc;
        int bcol = (pass == 1 ? KDIM : 0) + kc;
        uint32_t abase = sb + buf * STG;
        uint32_t bbase = abase + 16384;
        const __nv_bfloat16* ag = Apk + (size_t)(m0 + sr) * KD2 + acol + sc * 8;
        const __nv_bfloat16* wg = Wpk + (size_t)(n0 + sr) * KD2 + bcol + sc * 8;
#pragma unroll
        for (int i = 0; i < 4; i++) {
            int r = sr + i * 32;
            cp16(abase + r * 128 + soff, ag + (size_t)i * 32 * KD2);
            cp16(bbase + r * 128 + soff, wg + (size_t)i * 32 * KD2);
        }
    };

    int tile = blockIdx.x;
    if (tile >= NT) return;
    stage(tile, 0, 0);
    cp_commit();

#pragma unroll 1
    for (; tile < NT; tile += gridDim.x) {
        const int m0 = mbase + (tile / NX) * 128;
        const int n0 = (tile - (tile / NX) * NX) * 128;
        const int ntile = tile + gridDim.x;

        float acc[4][4][4];
#pragma unroll
        for (int i = 0; i < 4; i++)
#pragma unroll
            for (int j = 0; j < 4; j++)
#pragma unroll
                for (int q = 0; q < 4; q++) acc[i][j][q] = 0.f;

#pragma unroll 1
        for (int c = 0; c < NCH; c++) {
            bool more = (c + 1 < NCH) || (ntile < NT);
            if (c + 1 < NCH)      stage(tile, c + 1, (c + 1) & 1);
            else if (ntile < NT)  stage(ntile, 0, 0);   // NCH even -> buf 0
            if (more) { cp_commit(); cp_wait<1>(); }
            else      { cp_wait<0>(); }
            __syncthreads();
            uint32_t sAb = sb + (c & 1) * STG;
            uint32_t sBb = sAb + 16384;
#pragma unroll
            for (int ks = 0; ks < 4; ks++) {
                uint32_t afr[4][4], bfr[4][2];
#pragma unroll
                for (int i = 0; i < 4; i++) {
                    int r = wm * 64 + i * 16 + (lane & 15);
                    int cc = ks * 2 + (lane >> 4);
                    ldsm_x4(afr[i], sAb + r * 128 + ((cc ^ (r & 7)) * 16));
                }
#pragma unroll
                for (int j = 0; j < 4; j++) {
                    int r = wn * 32 + j * 8 + (lane & 7);
                    int cc = ks * 2 + ((lane >> 3) & 1);
                    ldsm_x2(bfr[j], sBb + r * 128 + ((cc ^ (r & 7)) * 16));
                }
#pragma unroll
                for (int i = 0; i < 4; i++)
#pragma unroll
                    for (int j = 0; j < 4; j++) mma16816(acc[i][j], afr[i], bfr[j]);
            }
            __syncthreads();
        }

        // epilogue (registers + global only; overlaps in-flight prefetch)
        const int g = lane >> 2;
        const int t2 = (lane & 3) * 2;
#pragma unroll
        for (int i = 0; i < 4; i++) {
#pragma unroll
            for (int j = 0; j < 4; j++) {
#pragma unroll
                for (int h = 0; h < 2; h++) {
                    int m = m0 + wm * 64 + i * 16 + g + h * 8;
                    int nb = n0 + wn * 32 + j * 8 + t2;
#pragma unroll
                    for (int e = 0; e < 2; e++) {
                        int n = nb + e;
                        float v = acc[i][j][h * 2 + e];
                        if (MODE == 0) {
                            if (n < 256) g_u[(size_t)m * 256 + n] = siluf(v);
                            else         g_gate[(size_t)m * 256 + n - 256] = v;
                        } else if (MODE == 1) {
                            float t = fmaxf(v + __ldg(&bias[n]), 0.f);
                            packsplit(t, &g_tpk[(size_t)m * 1024 + n],
                                         &g_tpk[(size_t)m * 1024 + 512 + n]);
                        } else {
                            g_s[(size_t)m * 256 + n] =
                                v + __ldg(&bias[n]) + g_y[(size_t)m * 256 + n];
                        }
                    }
                }
            }
        }
    }
}

// ---------------- K3: x_dbl = flow @ W_x^T, col-split across blockIdx.y ----------------
__global__ void __launch_bounds__(256) k_xdbl(const float* __restrict__ flow,
                                              const float* __restrict__ W_x,
                                              const float* __restrict__ W_dt,
                                              const float* __restrict__ b_dt, int boff) {
    __shared__ float sW[16][260];
    __shared__ float sF[16][260];
    __shared__ float sdlt[16][17];
    const int b0 = boff + blockIdx.x * 16;
    const int cb = blockIdx.y;
    const int tid = threadIdx.x;

#pragma unroll
    for (int i = 0; i < 4; i++) {
        int f = tid + i * 256;
        int r = f >> 6;
        int c4 = (f & 63) << 2;
        *(float4*)&sW[r][c4] = __ldg((const float4*)(W_x + (size_t)(cb * 16 + r) * 256 + c4));
        *(float4*)&sF[r][c4] = *(const float4*)(flow + (size_t)(b0 + r) * 256 + c4);
    }
    __syncthreads();

    {
        int row = tid >> 4;
        int col = tid & 15;
        float s = 0.f;
#pragma unroll 16
        for (int k = 0; k < 256; k += 4) {
            float4 w = *(const float4*)&sW[col][k];
            float4 f = *(const float4*)&sF[row][k];
            s += w.x * f.x + w.y * f.y + w.z * f.z + w.w * f.w;
        }
        int b = b0 + row;
        if (cb == 0)      sdlt[row][col] = s;
        else if (cb == 1) g_Bm[(size_t)b * 16 + col] = s;
        else              g_Cm[(size_t)b * 16 + col] = s;
    }

    if (cb != 0) return;
    __syncthreads();

    int d = tid;
    float4 wd0 = __ldg((const float4*)(W_dt + d * 16));
    float4 wd1 = __ldg((const float4*)(W_dt + d * 16 + 4));
    float4 wd2 = __ldg((const float4*)(W_dt + d * 16 + 8));
    float4 wd3 = __ldg((const float4*)(W_dt + d * 16 + 12));
    float bd = __ldg(&b_dt[d]);
#pragma unroll 4
    for (int row = 0; row < 16; row++) {
        const float* dl = &sdlt[row][0];
        float s = bd;
        s += wd0.x * dl[0]  + wd0.y * dl[1]  + wd0.z * dl[2]  + wd0.w * dl[3];
        s += wd1.x * dl[4]  + wd1.y * dl[5]  + wd1.z * dl[6]  + wd1.w * dl[7];
        s += wd2.x * dl[8]  + wd2.y * dl[9]  + wd2.z * dl[10] + wd2.w * dl[11];
        s += wd3.x * dl[12] + wd3.y * dl[13] + wd3.z * dl[14] + wd3.w * dl[15];
        g_delta[(size_t)(b0 + row) * 256 + d] = log1pf(expf(s));
    }
}

// ---------------- K4: SSM state update, smem-staged coalesced h I/O ----------------
__global__ void __launch_bounds__(256) k_mamba(const float* __restrict__ h,
                                               const float* __restrict__ Dv,
                                               float* __restrict__ h_new, int boff) {
    __shared__ float4 sh[256 * 5];     // row d at sh[d*5 + q], q=0..3 (1 float4 pad)
    __shared__ float sB[16], sC[16];
    const int b = boff + blockIdx.x;
    const int t = threadIdx.x;
    if (t < 16)       sB[t] = g_Bm[(size_t)b * 16 + t];
    else if (t < 32)  sC[t - 16] = g_Cm[(size_t)b * 16 + t - 16];

    const float4* hp = (const float4*)(h + (size_t)b * 4096);
#pragma unroll
    for (int j = 0; j < 4; j++) {
        int i = t + 256 * j;
        sh[(i >> 2) * 5 + (i & 3)] = __ldcs(&hp[i]);
    }
    __syncthreads();

    const int d = t;
    const size_t base = (size_t)b * 256 + d;
    const float delta = g_delta[base];
    const float u = g_u[base];
    const float du = delta * u;
    const float4* ap = (const float4*)(g_negA + d * 16);
    float y = 0.f;
#pragma unroll
    for (int q = 0; q < 4; q++) {
        float4 hv = sh[d * 5 + q];
        float4 al = __ldg(&ap[q]);
        float4 o;
        o.x = __expf(al.x * delta) * hv.x + du * sB[q * 4 + 0];
        o.y = __expf(al.y * delta) * hv.y + du * sB[q * 4 + 1];
        o.z = __expf(al.z * delta) * hv.z + du * sB[q * 4 + 2];
        o.w = __expf(al.w * delta) * hv.w + du * sB[q * 4 + 3];
        sh[d * 5 + q] = o;
        y += o.x * sC[q * 4 + 0] + o.y * sC[q * 4 + 1]
           + o.z * sC[q * 4 + 2] + o.w * sC[q * 4 + 3];
    }
    y += u * __ldg(&Dv[d]);
    float g = g_gate[base];
    float yv = y * siluf(g);
    g_y[base] = yv;
    packsplit(yv, &g_ypk[(size_t)b * 512 + d], &g_ypk[(size_t)b * 512 + 256 + d]);
    __syncthreads();

    float4* op = (float4*)(h_new + (size_t)b * 4096);
#pragma unroll
    for (int j = 0; j < 4; j++) {
        int i = t + 256 * j;
        __stcs(&op[i], sh[(i >> 2) * 5 + (i & 3)]);
    }
}

// ---------------- K7: LayerNorm + 4-way head + sigmoid; warp per row ----------------
__global__ void __launch_bounds__(256) k_head(const float* __restrict__ gamma,
                                              const float* __restrict__ beta,
                                              const float* __restrict__ W_bb,
                                              const float* __restrict__ b_bb,
                                              float* __restrict__ out, int boff) {
    int warp = threadIdx.x >> 5;
    int lane = threadIdx.x & 31;
    int b = boff + blockIdx.x * 8 + warp;
    const float* srow = g_s + (size_t)b * 256;

    float v[8];
    float sum = 0.f;
#pragma unroll
    for (int i = 0; i < 8; i++) { v[i] = srow[i * 32 + lane]; sum += v[i]; }
#pragma unroll
    for (int o = 16; o > 0; o >>= 1) sum += __shfl_xor_sync(0xffffffffu, sum, o);
    float mu = sum * (1.f / 256.f);
    float sq = 0.f;
#pragma unroll
    for (int i = 0; i < 8; i++) { float dd = v[i] - mu; sq += dd * dd; }
#pragma unroll
    for (int o = 16; o > 0; o >>= 1) sq += __shfl_xor_sync(0xffffffffu, sq, o);
    float inv = rsqrtf(sq * (1.f / 256.f) + 1e-5f);

    float a0 = 0.f, a1 = 0.f, a2 = 0.f, a3 = 0.f;
#pragma unroll
    for (int i = 0; i < 8; i++) {
        int c = i * 32 + lane;
        float sn = (v[i] - mu) * inv * __ldg(&gamma[c]) + __ldg(&beta[c]);
        a0 += sn * __ldg(&W_bb[c]);
        a1 += sn * __ldg(&W_bb[256 + c]);
        a2 += sn * __ldg(&W_bb[512 + c]);
        a3 += sn * __ldg(&W_bb[768 + c]);
    }
#pragma unroll
    for (int o = 16; o > 0; o >>= 1) {
        a0 += __shfl_xor_sync(0xffffffffu, a0, o);
        a1 += __shfl_xor_sync(0xffffffffu, a1, o);
        a2 += __shfl_xor_sync(0xffffffffu, a2, o);
        a3 += __shfl_xor_sync(0xffffffffu, a3, o);
    }
    if (lane == 0) {
        out[b * 4 + 0] = 1.f / (1.f + expf(-(a0 + __ldg(&b_bb[0]))));
        out[b * 4 + 1] = 1.f / (1.f + expf(-(a1 + __ldg(&b_bb[1]))));
        out[b * 4 + 2] = 1.f / (1.f + expf(-(a2 + __ldg(&b_bb[2]))));
        out[b * 4 + 3] = 1.f / (1.f + expf(-(a3 + __ldg(&b_bb[3]))));
    }
}

extern "C" void kernel_launch(void* const* d_in, const int* in_sizes, int n_in,
                              void* d_out, int out_size) {
    const float* x0    = (const float*)d_in[0];
    const float* flow  = (const float*)d_in[1];
    const float* h     = (const float*)d_in[2];
    const float* W_in  = (const float*)d_in[3];
    const float* W_x   = (const float*)d_in[4];
    const float* W_dt  = (const float*)d_in[5];
    const float* b_dt  = (const float*)d_in[6];
    const float* A_log = (const float*)d_in[7];
    const float* Dv    = (const float*)d_in[8];
    const float* W1    = (const float*)d_in[9];
    const float* b1    = (const float*)d_in[10];
    const float* W2    = (const float*)d_in[11];
    const float* b2    = (const float*)d_in[12];
    const float* gamma = (const float*)d_in[13];
    const float* beta  = (const float*)d_in[14];
    const float* W_bb  = (const float*)d_in[15];
    const float* b_bb  = (const float*)d_in[16];

    float* out   = (float*)d_out;                 // (B, 4)
    float* h_new = out + (size_t)BTOT * 4;        // (B, 256, 16)

    const int GSMEM = 2 * 32768 + 128;
    cudaFuncSetAttribute(k_hgemm<256, 512, 0>,
                         cudaFuncAttributeMaxDynamicSharedMemorySize, GSMEM);
    cudaFuncSetAttribute(k_hgemm<256, 512, 1>,
                         cudaFuncAttributeMaxDynamicSharedMemorySize, GSMEM);
    cudaFuncSetAttribute(k_hgemm<512, 256, 2>,
                         cudaFuncAttributeMaxDynamicSharedMemorySize, GSMEM);
    const int PGRID = 296;   // 148 SMs x 2 CTAs

    static cudaStream_t s1 = nullptr;
    static cudaEvent_t evFork = nullptr, evJoin = nullptr;
    if (s1 == nullptr) {
        cudaStreamCreateWithFlags(&s1, cudaStreamNonBlocking);
        cudaEventCreateWithFlags(&evFork, cudaEventDisableTiming);
        cudaEventCreateWithFlags(&evJoin, cudaEventDisableTiming);
    }

    // shared weight prep (serial, ~15us)
    k_prep<<<16, 256>>>(A_log);
    k_packw<<<512, 256>>>(W_in, 256, 0);
    k_packw<<<512, 256>>>(W1, 256, 1);
    k_packw<<<512, 256>>>(W2, 512, 2);
    cudaEventRecord(evFork, 0);
    cudaStreamWaitEvent(s1, evFork, 0);

    // 4 chunks, alternating streams (0,2 -> main; 1,3 -> s1) for phase offset
    for (int c = 0; c < 4; c++) {
        cudaStream_t st = (c & 1) ? s1 : (cudaStream_t)0;
        int boff = c * BCH;
        k_embed<<<BCH, 256, 0, st>>>(x0, boff);
        k_xdbl<<<dim3(BCH / 16, 3), 256, 0, st>>>(flow, W_x, W_dt, b_dt, boff);
        k_hgemm<256, 512, 0><<<PGRID, 256, GSMEM, st>>>((const float*)nullptr, boff);
        k_mamba<<<BCH, 256, 0, st>>>(h, Dv, h_new, boff);
        k_hgemm<256, 512, 1><<<PGRID, 256, GSMEM, st>>>(b1, boff);
        k_hgemm<512, 256, 2><<<PGRID, 256, GSMEM, st>>>(b2, boff);
        k_head<<<BCH / 8, 256, 0, st>>>(gamma, beta, W_bb, b_bb, out, boff);
    }

    cudaEventRecord(evJoin, s1);
    cudaStreamWaitEvent(0, evJoin, 0);
}

// round 16
// speedup vs baseline: 1.0125x; 1.0125x over previous
#include <cuda_runtime.h>
#include <cuda_bf16.h>
#include <math.h>
#include <stdint.h>

#define BTOT 32768
#define BHALF 16384
#define NDM 256
#define NDI 256
#define NDS 16
#define NFF 512

// ---- scratch (static device globals; no allocation) ----
__device__ float g_u[(size_t)BTOT*NDI];
__device__ float g_gate[(size_t)BTOT*NDI];
__device__ float g_delta[(size_t)BTOT*NDI];
__device__ float g_Bm[(size_t)BTOT*NDS];
__device__ float g_Cm[(size_t)BTOT*NDS];
__device__ float g_y[(size_t)BTOT*NDI];
__device__ float g_s[(size_t)BTOT*NDM];
__device__ float g_negA[NDI*NDS];

// packed split-bf16 activations: row = [hi(0..K-1) | lo(0..K-1)]
__device__ __nv_bfloat16 g_pospk[(size_t)BTOT*512];   // K=256
__device__ __nv_bfloat16 g_ypk[(size_t)BTOT*512];     // K=256
__device__ __nv_bfloat16 g_tpk[(size_t)BTOT*1024];    // K=512
// packed split-bf16 weights: row n = [hi(0..K-1) | lo(0..K-1)]
__device__ __nv_bfloat16 g_W0pk[512*512];
__device__ __nv_bfloat16 g_W1pk[512*512];
__device__ __nv_bfloat16 g_W2pk[256*1024];

__device__ __forceinline__ float siluf(float x) { return x / (1.f + __expf(-x)); }

__device__ __forceinline__ void packsplit(float v, __nv_bfloat16* hi_p, __nv_bfloat16* lo_p) {
    __nv_bfloat16 hi = __float2bfloat16(v);
    *hi_p = hi;
    *lo_p = __float2bfloat16(v - __bfloat162float(hi));
}

// ---------------- K0a: precompute -exp(A_log) ----------------
__global__ void k_prep(const float* __restrict__ A_log) {
    int i = blockIdx.x * 256 + threadIdx.x;
    g_negA[i] = -expf(A_log[i]);
}

// ---------------- K0b: pack weights to split bf16 ----------------
__global__ void k_packw(const float* __restrict__ W, int K, int sel) {
    int i = blockIdx.x * 256 + threadIdx.x;    // over rows*K
    int n = i / K, k = i - n * K;
    __nv_bfloat16* dst = sel == 0 ? g_W0pk : (sel == 1 ? g_W1pk : g_W2pk);
    float v = W[i];
    __nv_bfloat16 hi = __float2bfloat16(v);
    dst[(size_t)n * 2 * K + k] = hi;
    dst[(size_t)n * 2 * K + K + k] = __float2bfloat16(v - __bfloat162float(hi));
}

// ---------------- K1: sine embedding (writes packed bf16 split) ----------------
__global__ void __launch_bounds__(256) k_embed(const float* __restrict__ x0, int boff) {
    int b = boff + blockIdx.x;
    int c = threadIdx.x;
    int a = c >> 6;
    int w = c & 63;
    int j = w >> 1;
    float v = x0[b * 4 + a];
    float freq_inv = __expf(-(float)j * 0.28782313662425576f); // ln(10000)/32
    float p = v * 6.283185307179586f * freq_inv;
    float val = (w & 1) ? __cosf(p) : __sinf(p);
    packsplit(val, &g_pospk[(size_t)b * 512 + c], &g_pospk[(size_t)b * 512 + 256 + c]);
}

// ================= HMMA (mma.sync bf16) split-bf16 GEMM =================
// persistent CTAs + cp.async double buffering + cross-tile prefetch
__device__ __forceinline__ void ldsm_x4(uint32_t* a, uint32_t addr) {
    asm volatile("ldmatrix.sync.aligned.m8n8.x4.shared.b16 {%0,%1,%2,%3}, [%4];"
                 : "=r"(a[0]), "=r"(a[1]), "=r"(a[2]), "=r"(a[3]) : "r"(addr));
}
__device__ __forceinline__ void ldsm_x2(uint32_t* b, uint32_t addr) {
    asm volatile("ldmatrix.sync.aligned.m8n8.x2.shared.b16 {%0,%1}, [%2];"
                 : "=r"(b[0]), "=r"(b[1]) : "r"(addr));
}
__device__ __forceinline__ void mma16816(float* d, const uint32_t* a, const uint32_t* b) {
    asm volatile(
        "mma.sync.aligned.m16n8k16.row.col.f32.bf16.bf16.f32 "
        "{%0,%1,%2,%3}, {%4,%5,%6,%7}, {%8,%9}, {%0,%1,%2,%3};"
        : "+f"(d[0]), "+f"(d[1]), "+f"(d[2]), "+f"(d[3])
        : "r"(a[0]), "r"(a[1]), "r"(a[2]), "r"(a[3]), "r"(b[0]), "r"(b[1]));
}
__device__ __forceinline__ void cp16(uint32_t smem, const void* gmem) {
    asm volatile("cp.async.cg.shared.global [%0], [%1], 16;"
                 :: "r"(smem), "l"(gmem));
}
__device__ __forceinline__ void cp_commit() {
    asm volatile("cp.async.commit_group;");
}
template <int N>
__device__ __forceinline__ void cp_wait() {
    asm volatile("cp.async.wait_group %0;" :: "n"(N));
}

// MODE 0: A=g_pospk K=256, NOUT=512: n<256 -> g_u=silu(v), else g_gate=v
// MODE 1: A=g_ypk   K=256, NOUT=512: g_tpk = packsplit(relu(v + b1[n]))
// MODE 2: A=g_tpk   K=512, NOUT=256: g_s = v + b2[n] + g_y[m,n]
template <int KDIM, int NOUT, int MODE>
__global__ void __launch_bounds__(256) k_hgemm(const float* __restrict__ bias, int mbase) {
    extern __shared__ char smem_raw[];
    const __nv_bfloat16* __restrict__ Apk =
        MODE == 0 ? g_pospk : (MODE == 1 ? g_ypk : g_tpk);
    const __nv_bfloat16* __restrict__ Wpk =
        MODE == 0 ? g_W0pk : (MODE == 1 ? g_W1pk : g_W2pk);

    constexpr int KD2 = 2 * KDIM;
    constexpr int KCH = KDIM / 64;      // 64-col chunks per pass
    constexpr int NCH = 3 * KCH;        // total chunks over 3 passes (even)
    constexpr int STG = 32768;          // stage size: 16KB A + 16KB B
    constexpr int NX = NOUT / 128;      // tiles along N
    constexpr int NT = (BHALF / 128) * NX;

    const int tid = threadIdx.x;
    const int wid = tid >> 5;
    const int lane = tid & 31;
    const int wm = wid & 1;
    const int wn = wid >> 1;
    uint32_t sb = (uint32_t)__cvta_generic_to_shared(smem_raw);
    sb = (sb + 127u) & ~127u;

    const int sr = tid >> 3;
    const int sc = tid & 7;
    const uint32_t soff = (uint32_t)(((sc ^ (sr & 7)) * 16));

    auto stage = [&](int tile, int c, int buf) {
        int m0 = mbase + (tile / NX) * 128;
        int n0 = (tile - (tile / NX) * NX) * 128;
        int pass = c / KCH;
        int kc = (c - pass * KCH) * 64;
        int acol = (pass == 2 ? KDIM : 0) + kc;
        int bcol = (pass == 1 ? KDIM : 0) + kc;
        uint32_t abase = sb + buf * STG;
        uint32_t bbase = abase + 16384;
        const __nv_bfloat16* ag = Apk + (size_t)(m0 + sr) * KD2 + acol + sc * 8;
        const __nv_bfloat16* wg = Wpk + (size_t)(n0 + sr) * KD2 + bcol + sc * 8;
#pragma unroll
        for (int i = 0; i < 4; i++) {
            int r = sr + i * 32;
            cp16(abase + r * 128 + soff, ag + (size_t)i * 32 * KD2);
            cp16(bbase + r * 128 + soff, wg + (size_t)i * 32 * KD2);
        }
    };

    int tile = blockIdx.x;
    if (tile >= NT) return;
    stage(tile, 0, 0);
    cp_commit();

#pragma unroll 1
    for (; tile < NT; tile += gridDim.x) {
        const int m0 = mbase + (tile / NX) * 128;
        const int n0 = (tile - (tile / NX) * NX) * 128;
        const int ntile = tile + gridDim.x;

        float acc[4][4][4];
#pragma unroll
        for (int i = 0; i < 4; i++)
#pragma unroll
            for (int j = 0; j < 4; j++)
#pragma unroll
                for (int q = 0; q < 4; q++) acc[i][j][q] = 0.f;

#pragma unroll 1
        for (int c = 0; c < NCH; c++) {
            bool more = (c + 1 < NCH) || (ntile < NT);
            if (c + 1 < NCH)      stage(tile, c + 1, (c + 1) & 1);
            else if (ntile < NT)  stage(ntile, 0, 0);   // NCH even -> buf 0
            if (more) { cp_commit(); cp_wait<1>(); }
            else      { cp_wait<0>(); }
            __syncthreads();
            uint32_t sAb = sb + (c & 1) * STG;
            uint32_t sBb = sAb + 16384;
#pragma unroll
            for (int ks = 0; ks < 4; ks++) {
                uint32_t afr[4][4], bfr[4][2];
#pragma unroll
                for (int i = 0; i < 4; i++) {
                    int r = wm * 64 + i * 16 + (lane & 15);
                    int cc = ks * 2 + (lane >> 4);
                    ldsm_x4(afr[i], sAb + r * 128 + ((cc ^ (r & 7)) * 16));
                }
#pragma unroll
                for (int j = 0; j < 4; j++) {
                    int r = wn * 32 + j * 8 + (lane & 7);
                    int cc = ks * 2 + ((lane >> 3) & 1);
                    ldsm_x2(bfr[j], sBb + r * 128 + ((cc ^ (r & 7)) * 16));
                }
#pragma unroll
                for (int i = 0; i < 4; i++)
#pragma unroll
                    for (int j = 0; j < 4; j++) mma16816(acc[i][j], afr[i], bfr[j]);
            }
            __syncthreads();
        }

        // epilogue (registers + global only; overlaps in-flight prefetch)
        const int g = lane >> 2;
        const int t2 = (lane & 3) * 2;
#pragma unroll
        for (int i = 0; i < 4; i++) {
#pragma unroll
            for (int j = 0; j < 4; j++) {
#pragma unroll
                for (int h = 0; h < 2; h++) {
                    int m = m0 + wm * 64 + i * 16 + g + h * 8;
                    int nb = n0 + wn * 32 + j * 8 + t2;
#pragma unroll
                    for (int e = 0; e < 2; e++) {
                        int n = nb + e;
                        float v = acc[i][j][h * 2 + e];
                        if (MODE == 0) {
                            if (n < 256) g_u[(size_t)m * 256 + n] = siluf(v);
                            else         g_gate[(size_t)m * 256 + n - 256] = v;
                        } else if (MODE == 1) {
                            float t = fmaxf(v + __ldg(&bias[n]), 0.f);
                            packsplit(t, &g_tpk[(size_t)m * 1024 + n],
                                         &g_tpk[(size_t)m * 1024 + 512 + n]);
                        } else {
                            g_s[(size_t)m * 256 + n] =
                                v + __ldg(&bias[n]) + g_y[(size_t)m * 256 + n];
                        }
                    }
                }
            }
        }
    }
}

// ---------------- K3: x_dbl = flow @ W_x^T, col-split across blockIdx.y ----------------
__global__ void __launch_bounds__(256) k_xdbl(const float* __restrict__ flow,
                                              const float* __restrict__ W_x,
                                              const float* __restrict__ W_dt,
                                              const float* __restrict__ b_dt, int boff) {
    __shared__ float sW[16][260];
    __shared__ float sF[16][260];
    __shared__ float sdlt[16][17];
    const int b0 = boff + blockIdx.x * 16;
    const int cb = blockIdx.y;
    const int tid = threadIdx.x;

#pragma unroll
    for (int i = 0; i < 4; i++) {
        int f = tid + i * 256;
        int r = f >> 6;
        int c4 = (f & 63) << 2;
        *(float4*)&sW[r][c4] = __ldg((const float4*)(W_x + (size_t)(cb * 16 + r) * 256 + c4));
        *(float4*)&sF[r][c4] = *(const float4*)(flow + (size_t)(b0 + r) * 256 + c4);
    }
    __syncthreads();

    {
        int row = tid >> 4;
        int col = tid & 15;
        float s = 0.f;
#pragma unroll 16
        for (int k = 0; k < 256; k += 4) {
            float4 w = *(const float4*)&sW[col][k];
            float4 f = *(const float4*)&sF[row][k];
            s += w.x * f.x + w.y * f.y + w.z * f.z + w.w * f.w;
        }
        int b = b0 + row;
        if (cb == 0)      sdlt[row][col] = s;
        else if (cb == 1) g_Bm[(size_t)b * 16 + col] = s;
        else              g_Cm[(size_t)b * 16 + col] = s;
    }

    if (cb != 0) return;
    __syncthreads();

    int d = tid;
    float4 wd0 = __ldg((const float4*)(W_dt + d * 16));
    float4 wd1 = __ldg((const float4*)(W_dt + d * 16 + 4));
    float4 wd2 = __ldg((const float4*)(W_dt + d * 16 + 8));
    float4 wd3 = __ldg((const float4*)(W_dt + d * 16 + 12));
    float bd = __ldg(&b_dt[d]);
#pragma unroll 4
    for (int row = 0; row < 16; row++) {
        const float* dl = &sdlt[row][0];
        float s = bd;
        s += wd0.x * dl[0]  + wd0.y * dl[1]  + wd0.z * dl[2]  + wd0.w * dl[3];
        s += wd1.x * dl[4]  + wd1.y * dl[5]  + wd1.z * dl[6]  + wd1.w * dl[7];
        s += wd2.x * dl[8]  + wd2.y * dl[9]  + wd2.z * dl[10] + wd2.w * dl[11];
        s += wd3.x * dl[12] + wd3.y * dl[13] + wd3.z * dl[14] + wd3.w * dl[15];
        g_delta[(size_t)(b0 + row) * 256 + d] = log1pf(expf(s));
    }
}

// ---------------- K4: SSM state update, smem-staged coalesced h I/O ----------------
__global__ void __launch_bounds__(256) k_mamba(const float* __restrict__ h,
                                               const float* __restrict__ Dv,
                                               float* __restrict__ h_new, int boff) {
    __shared__ float4 sh[256 * 5];     // row d at sh[d*5 + q], q=0..3 (1 float4 pad)
    __shared__ float sB[16], sC[16];
    const int b = boff + blockIdx.x;
    const int t = threadIdx.x;
    if (t < 16)       sB[t] = g_Bm[(size_t)b * 16 + t];
    else if (t < 32)  sC[t - 16] = g_Cm[(size_t)b * 16 + t - 16];

    const float4* hp = (const float4*)(h + (size_t)b * 4096);
#pragma unroll
    for (int j = 0; j < 4; j++) {
        int i = t + 256 * j;
        sh[(i >> 2) * 5 + (i & 3)] = __ldcs(&hp[i]);
    }
    __syncthreads();

    const int d = t;
    const size_t base = (size_t)b * 256 + d;
    const float delta = g_delta[base];
    const float u = g_u[base];
    const float du = delta * u;
    const float4* ap = (const float4*)(g_negA + d * 16);
    float y = 0.f;
#pragma unroll
    for (int q = 0; q < 4; q++) {
        float4 hv = sh[d * 5 + q];
        float4 al = __ldg(&ap[q]);
        float4 o;
        o.x = __expf(al.x * delta) * hv.x + du * sB[q * 4 + 0];
        o.y = __expf(al.y * delta) * hv.y + du * sB[q * 4 + 1];
        o.z = __expf(al.z * delta) * hv.z + du * sB[q * 4 + 2];
        o.w = __expf(al.w * delta) * hv.w + du * sB[q * 4 + 3];
        sh[d * 5 + q] = o;
        y += o.x * sC[q * 4 + 0] + o.y * sC[q * 4 + 1]
           + o.z * sC[q * 4 + 2] + o.w * sC[q * 4 + 3];
    }
    y += u * __ldg(&Dv[d]);
    float g = g_gate[base];
    float yv = y * siluf(g);
    g_y[base] = yv;
    packsplit(yv, &g_ypk[(size_t)b * 512 + d], &g_ypk[(size_t)b * 512 + 256 + d]);
    __syncthreads();

    float4* op = (float4*)(h_new + (size_t)b * 4096);
#pragma unroll
    for (int j = 0; j < 4; j++) {
        int i = t + 256 * j;
        __stcs(&op[i], sh[(i >> 2) * 5 + (i & 3)]);
    }
}

// ---------------- K7: LayerNorm + 4-way head + sigmoid; warp per row ----------------
__global__ void __launch_bounds__(256) k_head(const float* __restrict__ gamma,
                                              const float* __restrict__ beta,
                                              const float* __restrict__ W_bb,
                                              const float* __restrict__ b_bb,
                                              float* __restrict__ out, int boff) {
    int warp = threadIdx.x >> 5;
    int lane = threadIdx.x & 31;
    int b = boff + blockIdx.x * 8 + warp;
    const float* srow = g_s + (size_t)b * 256;

    float v[8];
    float sum = 0.f;
#pragma unroll
    for (int i = 0; i < 8; i++) { v[i] = srow[i * 32 + lane]; sum += v[i]; }
#pragma unroll
    for (int o = 16; o > 0; o >>= 1) sum += __shfl_xor_sync(0xffffffffu, sum, o);
    float mu = sum * (1.f / 256.f);
    float sq = 0.f;
#pragma unroll
    for (int i = 0; i < 8; i++) { float dd = v[i] - mu; sq += dd * dd; }
#pragma unroll
    for (int o = 16; o > 0; o >>= 1) sq += __shfl_xor_sync(0xffffffffu, sq, o);
    float inv = rsqrtf(sq * (1.f / 256.f) + 1e-5f);

    float a0 = 0.f, a1 = 0.f, a2 = 0.f, a3 = 0.f;
#pragma unroll
    for (int i = 0; i < 8; i++) {
        int c = i * 32 + lane;
        float sn = (v[i] - mu) * inv * __ldg(&gamma[c]) + __ldg(&beta[c]);
        a0 += sn * __ldg(&W_bb[c]);
        a1 += sn * __ldg(&W_bb[256 + c]);
        a2 += sn * __ldg(&W_bb[512 + c]);
        a3 += sn * __ldg(&W_bb[768 + c]);
    }
#pragma unroll
    for (int o = 16; o > 0; o >>= 1) {
        a0 += __shfl_xor_sync(0xffffffffu, a0, o);
        a1 += __shfl_xor_sync(0xffffffffu, a1, o);
        a2 += __shfl_xor_sync(0xffffffffu, a2, o);
        a3 += __shfl_xor_sync(0xffffffffu, a3, o);
    }
    if (lane == 0) {
        out[b * 4 + 0] = 1.f / (1.f + expf(-(a0 + __ldg(&b_bb[0]))));
        out[b * 4 + 1] = 1.f / (1.f + expf(-(a1 + __ldg(&b_bb[1]))));
        out[b * 4 + 2] = 1.f / (1.f + expf(-(a2 + __ldg(&b_bb[2]))));
        out[b * 4 + 3] = 1.f / (1.f + expf(-(a3 + __ldg(&b_bb[3]))));
    }
}

extern "C" void kernel_launch(void* const* d_in, const int* in_sizes, int n_in,
                              void* d_out, int out_size) {
    const float* x0    = (const float*)d_in[0];
    const float* flow  = (const float*)d_in[1];
    const float* h     = (const float*)d_in[2];
    const float* W_in  = (const float*)d_in[3];
    const float* W_x   = (const float*)d_in[4];
    const float* W_dt  = (const float*)d_in[5];
    const float* b_dt  = (const float*)d_in[6];
    const float* A_log = (const float*)d_in[7];
    const float* Dv    = (const float*)d_in[8];
    const float* W1    = (const float*)d_in[9];
    const float* b1    = (const float*)d_in[10];
    const float* W2    = (const float*)d_in[11];
    const float* b2    = (const float*)d_in[12];
    const float* gamma = (const float*)d_in[13];
    const float* beta  = (const float*)d_in[14];
    const float* W_bb  = (const float*)d_in[15];
    const float* b_bb  = (const float*)d_in[16];

    float* out   = (float*)d_out;                 // (B, 4)
    float* h_new = out + (size_t)BTOT * 4;        // (B, 256, 16)

    const int GSMEM = 2 * 32768 + 128;
    cudaFuncSetAttribute(k_hgemm<256, 512, 0>,
                         cudaFuncAttributeMaxDynamicSharedMemorySize, GSMEM);
    cudaFuncSetAttribute(k_hgemm<256, 512, 1>,
                         cudaFuncAttributeMaxDynamicSharedMemorySize, GSMEM);
    cudaFuncSetAttribute(k_hgemm<512, 256, 2>,
                         cudaFuncAttributeMaxDynamicSharedMemorySize, GSMEM);
    const int PGRID = 296;   // 148 SMs x 2 CTAs

    static cudaStream_t s1 = nullptr;
    static cudaEvent_t evFork = nullptr, evJoin = nullptr, evPhase = nullptr;
    if (s1 == nullptr) {
        cudaStreamCreateWithFlags(&s1, cudaStreamNonBlocking);
        cudaEventCreateWithFlags(&evFork, cudaEventDisableTiming);
        cudaEventCreateWithFlags(&evJoin, cudaEventDisableTiming);
        cudaEventCreateWithFlags(&evPhase, cudaEventDisableTiming);
    }

    // shared weight prep (serial, ~15us)
    k_prep<<<16, 256>>>(A_log);
    k_packw<<<512, 256>>>(W_in, 256, 0);
    k_packw<<<512, 256>>>(W1, 256, 1);
    k_packw<<<512, 256>>>(W2, 512, 2);
    cudaEventRecord(evFork, 0);
    cudaStreamWaitEvent(s1, evFork, 0);

    // ---- half 1 prologue on side stream (runs under main's G0) ----
    k_embed<<<BHALF, 256, 0, s1>>>(x0, BHALF);
    k_xdbl<<<dim3(BHALF / 16, 3), 256, 0, s1>>>(flow, W_x, W_dt, b_dt, BHALF);

    // ---- half 0 on main stream ----
    k_embed<<<BHALF, 256>>>(x0, 0);
    k_xdbl<<<dim3(BHALF / 16, 3), 256>>>(flow, W_x, W_dt, b_dt, 0);
    k_hgemm<256, 512, 0><<<PGRID, 256, GSMEM>>>((const float*)nullptr, 0);
    cudaEventRecord(evPhase, 0);              // phase offset: s1's G0 starts after main's G0
    k_mamba<<<BHALF, 256>>>(h, Dv, h_new, 0);   // DRAM-bound, overlaps s1's G0
    k_hgemm<256, 512, 1><<<PGRID, 256, GSMEM>>>(b1, 0);
    k_hgemm<512, 256, 2><<<PGRID, 256, GSMEM>>>(b2, 0);
    k_head<<<BHALF / 8, 256>>>(gamma, beta, W_bb, b_bb, out, 0);

    // ---- half 1 main body on side stream, phase-shifted ----
    cudaStreamWaitEvent(s1, evPhase, 0);
    k_hgemm<256, 512, 0><<<PGRID, 256, GSMEM, s1>>>((const float*)nullptr, BHALF);
    k_mamba<<<BHALF, 256, 0, s1>>>(h, Dv, h_new, BHALF);  // overlaps main's G1/G2
    k_hgemm<256, 512, 1><<<PGRID, 256, GSMEM, s1>>>(b1, BHALF);
    k_hgemm<512, 256, 2><<<PGRID, 256, GSMEM, s1>>>(b2, BHALF);
    k_head<<<BHALF / 8, 256, 0, s1>>>(gamma, beta, W_bb, b_bb, out, BHALF);

    cudaEventRecord(evJoin, s1);
    cudaStreamWaitEvent(0, evJoin, 0);
}

// round 17
// speedup vs baseline: 1.0624x; 1.0493x over previous
#include <cuda_runtime.h>
#include <cuda_bf16.h>
#include <math.h>
#include <stdint.h>

#define BTOT 32768
#define BHALF 16384
#define NDM 256
#define NDI 256
#define NDS 16
#define NFF 512

// ---- scratch (static device globals; no allocation) ----
__device__ float g_u[(size_t)BTOT*NDI];
__device__ float g_gate[(size_t)BTOT*NDI];
__device__ float g_delta[(size_t)BTOT*NDI];
__device__ float g_Bm[(size_t)BTOT*NDS];
__device__ float g_Cm[(size_t)BTOT*NDS];
__device__ float g_y[(size_t)BTOT*NDI];
__device__ float g_s[(size_t)BTOT*NDM];
__device__ float g_negA[NDI*NDS];

// packed split-bf16 activations: row = [hi(0..K-1) | lo(0..K-1)]
__device__ __nv_bfloat16 g_pospk[(size_t)BTOT*512];   // K=256
__device__ __nv_bfloat16 g_ypk[(size_t)BTOT*512];     // K=256
__device__ __nv_bfloat16 g_tpk[(size_t)BTOT*1024];    // K=512
// packed split-bf16 weights: row n = [hi(0..K-1) | lo(0..K-1)]
__device__ __nv_bfloat16 g_W0pk[512*512];
__device__ __nv_bfloat16 g_W1pk[512*512];
__device__ __nv_bfloat16 g_W2pk[256*1024];

__device__ __forceinline__ float siluf(float x) { return x / (1.f + __expf(-x)); }

__device__ __forceinline__ void packsplit(float v, __nv_bfloat16* hi_p, __nv_bfloat16* lo_p) {
    __nv_bfloat16 hi = __float2bfloat16(v);
    *hi_p = hi;
    *lo_p = __float2bfloat16(v - __bfloat162float(hi));
}

// ---------------- K0a: precompute -exp(A_log) ----------------
__global__ void k_prep(const float* __restrict__ A_log) {
    int i = blockIdx.x * 256 + threadIdx.x;
    g_negA[i] = -expf(A_log[i]);
}

// ---------------- K0b: pack weights to split bf16 ----------------
__global__ void k_packw(const float* __restrict__ W, int K, int sel) {
    int i = blockIdx.x * 256 + threadIdx.x;    // over rows*K
    int n = i / K, k = i - n * K;
    __nv_bfloat16* dst = sel == 0 ? g_W0pk : (sel == 1 ? g_W1pk : g_W2pk);
    float v = W[i];
    __nv_bfloat16 hi = __float2bfloat16(v);
    dst[(size_t)n * 2 * K + k] = hi;
    dst[(size_t)n * 2 * K + K + k] = __float2bfloat16(v - __bfloat162float(hi));
}

// ---------------- K1: sine embedding; one thread per (sin,cos) pair ----------------
__global__ void __launch_bounds__(256) k_embed(const float* __restrict__ x0, int boff) {
    int idx = blockIdx.x * 256 + threadIdx.x;   // over BHALF*128 pairs
    int b = boff + (idx >> 7);
    int pr = idx & 127;
    int a = pr >> 5;            // axis 0..3
    int j = pr & 31;            // freq index
    float v = x0[b * 4 + a];
    float freq_inv = __expf(-(float)j * 0.28782313662425576f); // ln(10000)/32
    float p = v * 6.283185307179586f * freq_inv;
    float sv, cv;
    __sincosf(p, &sv, &cv);
    int c0 = a * 64 + 2 * j;
    __nv_bfloat16* hi = &g_pospk[(size_t)b * 512];
    __nv_bfloat16* lo = hi + 256;
    packsplit(sv, hi + c0, lo + c0);
    packsplit(cv, hi + c0 + 1, lo + c0 + 1);
}

// ================= HMMA (mma.sync bf16) split-bf16 GEMM =================
// persistent CTAs + cp.async double buffering + cross-tile prefetch
__device__ __forceinline__ void ldsm_x4(uint32_t* a, uint32_t addr) {
    asm volatile("ldmatrix.sync.aligned.m8n8.x4.shared.b16 {%0,%1,%2,%3}, [%4];"
                 : "=r"(a[0]), "=r"(a[1]), "=r"(a[2]), "=r"(a[3]) : "r"(addr));
}
__device__ __forceinline__ void ldsm_x2(uint32_t* b, uint32_t addr) {
    asm volatile("ldmatrix.sync.aligned.m8n8.x2.shared.b16 {%0,%1}, [%2];"
                 : "=r"(b[0]), "=r"(b[1]) : "r"(addr));
}
__device__ __forceinline__ void mma16816(float* d, const uint32_t* a, const uint32_t* b) {
    asm volatile(
        "mma.sync.aligned.m16n8k16.row.col.f32.bf16.bf16.f32 "
        "{%0,%1,%2,%3}, {%4,%5,%6,%7}, {%8,%9}, {%0,%1,%2,%3};"
        : "+f"(d[0]), "+f"(d[1]), "+f"(d[2]), "+f"(d[3])
        : "r"(a[0]), "r"(a[1]), "r"(a[2]), "r"(a[3]), "r"(b[0]), "r"(b[1]));
}
__device__ __forceinline__ void cp16(uint32_t smem, const void* gmem) {
    asm volatile("cp.async.cg.shared.global [%0], [%1], 16;"
                 :: "r"(smem), "l"(gmem));
}
__device__ __forceinline__ void cp_commit() {
    asm volatile("cp.async.commit_group;");
}
template <int N>
__device__ __forceinline__ void cp_wait() {
    asm volatile("cp.async.wait_group %0;" :: "n"(N));
}

// MODE 0: A=g_pospk K=256, NOUT=512: n<256 -> g_u=silu(v), else g_gate=v
// MODE 1: A=g_ypk   K=256, NOUT=512: g_tpk = packsplit(relu(v + b1[n]))
// MODE 2: A=g_tpk   K=512, NOUT=256: g_s = v + b2[n] + g_y[m,n]
template <int KDIM, int NOUT, int MODE>
__global__ void __launch_bounds__(256) k_hgemm(const float* __restrict__ bias, int mbase) {
    extern __shared__ char smem_raw[];
    const __nv_bfloat16* __restrict__ Apk =
        MODE == 0 ? g_pospk : (MODE == 1 ? g_ypk : g_tpk);
    const __nv_bfloat16* __restrict__ Wpk =
        MODE == 0 ? g_W0pk : (MODE == 1 ? g_W1pk : g_W2pk);

    constexpr int KD2 = 2 * KDIM;
    constexpr int KCH = KDIM / 64;      // 64-col chunks per pass
    constexpr int NCH = 3 * KCH;        // total chunks over 3 passes (even)
    constexpr int STG = 32768;          // stage size: 16KB A + 16KB B
    constexpr int NX = NOUT / 128;      // tiles along N
    constexpr int NT = (BHALF / 128) * NX;

    const int tid = threadIdx.x;
    const int wid = tid >> 5;
    const int lane = tid & 31;
    const int wm = wid & 1;
    const int wn = wid >> 1;
    uint32_t sb = (uint32_t)__cvta_generic_to_shared(smem_raw);
    sb = (sb + 127u) & ~127u;

    const int sr = tid >> 3;
    const int sc = tid & 7;
    const uint32_t soff = (uint32_t)(((sc ^ (sr & 7)) * 16));

    auto stage = [&](int tile, int c, int buf) {
        int m0 = mbase + (tile / NX) * 128;
        int n0 = (tile - (tile / NX) * NX) * 128;
        int pass = c / KCH;
        int kc = (c - pass * KCH) * 64;
        int acol = (pass == 2 ? KDIM : 0) + kc;
        int bcol = (pass == 1 ? KDIM : 0) + kc;
        uint32_t abase = sb + buf * STG;
        uint32_t bbase = abase + 16384;
        const __nv_bfloat16* ag = Apk + (size_t)(m0 + sr) * KD2 + acol + sc * 8;
        const __nv_bfloat16* wg = Wpk + (size_t)(n0 + sr) * KD2 + bcol + sc * 8;
#pragma unroll
        for (int i = 0; i < 4; i++) {
            int r = sr + i * 32;
            cp16(abase + r * 128 + soff, ag + (size_t)i * 32 * KD2);
            cp16(bbase + r * 128 + soff, wg + (size_t)i * 32 * KD2);
        }
    };

    int tile = blockIdx.x;
    if (tile >= NT) return;
    stage(tile, 0, 0);
    cp_commit();

#pragma unroll 1
    for (; tile < NT; tile += gridDim.x) {
        const int m0 = mbase + (tile / NX) * 128;
        const int n0 = (tile - (tile / NX) * NX) * 128;
        const int ntile = tile + gridDim.x;

        float acc[4][4][4];
#pragma unroll
        for (int i = 0; i < 4; i++)
#pragma unroll
            for (int j = 0; j < 4; j++)
#pragma unroll
                for (int q = 0; q < 4; q++) acc[i][j][q] = 0.f;

#pragma unroll 1
        for (int c = 0; c < NCH; c++) {
            // chunk c is the only pending group here
            cp_wait<0>();
            __syncthreads();          // data visible + all warps done reading buf (c-1)&1
            if (c + 1 < NCH)      { stage(tile, c + 1, (c + 1) & 1); cp_commit(); }
            else if (ntile < NT)  { stage(ntile, 0, 0); cp_commit(); }  // NCH even -> buf 0
            uint32_t sAb = sb + (c & 1) * STG;
            uint32_t sBb = sAb + 16384;
#pragma unroll
            for (int ks = 0; ks < 4; ks++) {
                uint32_t afr[4][4], bfr[4][2];
#pragma unroll
                for (int i = 0; i < 4; i++) {
                    int r = wm * 64 + i * 16 + (lane & 15);
                    int cc = ks * 2 + (lane >> 4);
                    ldsm_x4(afr[i], sAb + r * 128 + ((cc ^ (r & 7)) * 16));
                }
#pragma unroll
                for (int j = 0; j < 4; j++) {
                    int r = wn * 32 + j * 8 + (lane & 7);
                    int cc = ks * 2 + ((lane >> 3) & 1);
                    ldsm_x2(bfr[j], sBb + r * 128 + ((cc ^ (r & 7)) * 16));
                }
#pragma unroll
                for (int i = 0; i < 4; i++)
#pragma unroll
                    for (int j = 0; j < 4; j++) mma16816(acc[i][j], afr[i], bfr[j]);
            }
        }
        __syncthreads();   // protect buf 0 (next tile's chunk 0 is in flight; epilogue doesn't touch smem)

        // epilogue (registers + global only; overlaps in-flight prefetch)
        const int g = lane >> 2;
        const int t2 = (lane & 3) * 2;
#pragma unroll
        for (int i = 0; i < 4; i++) {
#pragma unroll
            for (int j = 0; j < 4; j++) {
#pragma unroll
                for (int h = 0; h < 2; h++) {
                    int m = m0 + wm * 64 + i * 16 + g + h * 8;
                    int nb = n0 + wn * 32 + j * 8 + t2;
#pragma unroll
                    for (int e = 0; e < 2; e++) {
                        int n = nb + e;
                        float v = acc[i][j][h * 2 + e];
                        if (MODE == 0) {
                            if (n < 256) g_u[(size_t)m * 256 + n] = siluf(v);
                            else         g_gate[(size_t)m * 256 + n - 256] = v;
                        } else if (MODE == 1) {
                            float t = fmaxf(v + __ldg(&bias[n]), 0.f);
                            packsplit(t, &g_tpk[(size_t)m * 1024 + n],
                                         &g_tpk[(size_t)m * 1024 + 512 + n]);
                        } else {
                            g_s[(size_t)m * 256 + n] =
                                v + __ldg(&bias[n]) + g_y[(size_t)m * 256 + n];
                        }
                    }
                }
            }
        }
    }
}

// ---------------- K3: x_dbl = flow @ W_x^T, col-split across blockIdx.y ----------------
__global__ void __launch_bounds__(256) k_xdbl(const float* __restrict__ flow,
                                              const float* __restrict__ W_x,
                                              const float* __restrict__ W_dt,
                                              const float* __restrict__ b_dt, int boff) {
    __shared__ float sW[16][260];
    __shared__ float sF[16][260];
    __shared__ float sdlt[16][17];
    const int b0 = boff + blockIdx.x * 16;
    const int cb = blockIdx.y;
    const int tid = threadIdx.x;

#pragma unroll
    for (int i = 0; i < 4; i++) {
        int f = tid + i * 256;
        int r = f >> 6;
        int c4 = (f & 63) << 2;
        *(float4*)&sW[r][c4] = __ldg((const float4*)(W_x + (size_t)(cb * 16 + r) * 256 + c4));
        *(float4*)&sF[r][c4] = *(const float4*)(flow + (size_t)(b0 + r) * 256 + c4);
    }
    __syncthreads();

    {
        int row = tid >> 4;
        int col = tid & 15;
        float s = 0.f;
#pragma unroll 16
        for (int k = 0; k < 256; k += 4) {
            float4 w = *(const float4*)&sW[col][k];
            float4 f = *(const float4*)&sF[row][k];
            s += w.x * f.x + w.y * f.y + w.z * f.z + w.w * f.w;
        }
        int b = b0 + row;
        if (cb == 0)      sdlt[row][col] = s;
        else if (cb == 1) g_Bm[(size_t)b * 16 + col] = s;
        else              g_Cm[(size_t)b * 16 + col] = s;
    }

    if (cb != 0) return;
    __syncthreads();

    int d = tid;
    float4 wd0 = __ldg((const float4*)(W_dt + d * 16));
    float4 wd1 = __ldg((const float4*)(W_dt + d * 16 + 4));
    float4 wd2 = __ldg((const float4*)(W_dt + d * 16 + 8));
    float4 wd3 = __ldg((const float4*)(W_dt + d * 16 + 12));
    float bd = __ldg(&b_dt[d]);
#pragma unroll 4
    for (int row = 0; row < 16; row++) {
        const float* dl = &sdlt[row][0];
        float s = bd;
        s += wd0.x * dl[0]  + wd0.y * dl[1]  + wd0.z * dl[2]  + wd0.w * dl[3];
        s += wd1.x * dl[4]  + wd1.y * dl[5]  + wd1.z * dl[6]  + wd1.w * dl[7];
        s += wd2.x * dl[8]  + wd2.y * dl[9]  + wd2.z * dl[10] + wd2.w * dl[11];
        s += wd3.x * dl[12] + wd3.y * dl[13] + wd3.z * dl[14] + wd3.w * dl[15];
        g_delta[(size_t)(b0 + row) * 256 + d] = log1pf(expf(s));
    }
}

// ---------------- K4: SSM state update, smem-staged coalesced h I/O ----------------
__global__ void __launch_bounds__(256) k_mamba(const float* __restrict__ h,
                                               const float* __restrict__ Dv,
                                               float* __restrict__ h_new, int boff) {
    __shared__ float4 sh[256 * 5];     // row d at sh[d*5 + q], q=0..3 (1 float4 pad)
    __shared__ float sB[16], sC[16];
    const int b = boff + blockIdx.x;
    const int t = threadIdx.x;
    if (t < 16)       sB[t] = g_Bm[(size_t)b * 16 + t];
    else if (t < 32)  sC[t - 16] = g_Cm[(size_t)b * 16 + t - 16];

    const float4* hp = (const float4*)(h + (size_t)b * 4096);
#pragma unroll
    for (int j = 0; j < 4; j++) {
        int i = t + 256 * j;
        sh[(i >> 2) * 5 + (i & 3)] = __ldcs(&hp[i]);
    }
    __syncthreads();

    const int d = t;
    const size_t base = (size_t)b * 256 + d;
    const float delta = g_delta[base];
    const float u = g_u[base];
    const float du = delta * u;
    const float4* ap = (const float4*)(g_negA + d * 16);
    float y = 0.f;
#pragma unroll
    for (int q = 0; q < 4; q++) {
        float4 hv = sh[d * 5 + q];
        float4 al = __ldg(&ap[q]);
        float4 o;
        o.x = __expf(al.x * delta) * hv.x + du * sB[q * 4 + 0];
        o.y = __expf(al.y * delta) * hv.y + du * sB[q * 4 + 1];
        o.z = __expf(al.z * delta) * hv.z + du * sB[q * 4 + 2];
        o.w = __expf(al.w * delta) * hv.w + du * sB[q * 4 + 3];
        sh[d * 5 + q] = o;
        y += o.x * sC[q * 4 + 0] + o.y * sC[q * 4 + 1]
           + o.z * sC[q * 4 + 2] + o.w * sC[q * 4 + 3];
    }
    y += u * __ldg(&Dv[d]);
    float g = g_gate[base];
    float yv = y * siluf(g);
    g_y[base] = yv;
    packsplit(yv, &g_ypk[(size_t)b * 512 + d], &g_ypk[(size_t)b * 512 + 256 + d]);
    __syncthreads();

    float4* op = (float4*)(h_new + (size_t)b * 4096);
#pragma unroll
    for (int j = 0; j < 4; j++) {
        int i = t + 256 * j;
        __stcs(&op[i], sh[(i >> 2) * 5 + (i & 3)]);
    }
}

// ---------------- K7: LayerNorm + 4-way head + sigmoid; warp per row ----------------
__global__ void __launch_bounds__(256) k_head(const float* __restrict__ gamma,
                                              const float* __restrict__ beta,
                                              const float* __restrict__ W_bb,
                                              const float* __restrict__ b_bb,
                                              float* __restrict__ out, int boff) {
    int warp = threadIdx.x >> 5;
    int lane = threadIdx.x & 31;
    int b = boff + blockIdx.x * 8 + warp;
    const float* srow = g_s + (size_t)b * 256;

    float v[8];
    float sum = 0.f;
#pragma unroll
    for (int i = 0; i < 8; i++) { v[i] = srow[i * 32 + lane]; sum += v[i]; }
#pragma unroll
    for (int o = 16; o > 0; o >>= 1) sum += __shfl_xor_sync(0xffffffffu, sum, o);
    float mu = sum * (1.f / 256.f);
    float sq = 0.f;
#pragma unroll
    for (int i = 0; i < 8; i++) { float dd = v[i] - mu; sq += dd * dd; }
#pragma unroll
    for (int o = 16; o > 0; o >>= 1) sq += __shfl_xor_sync(0xffffffffu, sq, o);
    float inv = rsqrtf(sq * (1.f / 256.f) + 1e-5f);

    float a0 = 0.f, a1 = 0.f, a2 = 0.f, a3 = 0.f;
#pragma unroll
    for (int i = 0; i < 8; i++) {
        int c = i * 32 + lane;
        float sn = (v[i] - mu) * inv * __ldg(&gamma[c]) + __ldg(&beta[c]);
        a0 += sn * __ldg(&W_bb[c]);
        a1 += sn * __ldg(&W_bb[256 + c]);
        a2 += sn * __ldg(&W_bb[512 + c]);
        a3 += sn * __ldg(&W_bb[768 + c]);
    }
#pragma unroll
    for (int o = 16; o > 0; o >>= 1) {
        a0 += __shfl_xor_sync(0xffffffffu, a0, o);
        a1 += __shfl_xor_sync(0xffffffffu, a1, o);
        a2 += __shfl_xor_sync(0xffffffffu, a2, o);
        a3 += __shfl_xor_sync(0xffffffffu, a3, o);
    }
    if (lane == 0) {
        out[b * 4 + 0] = 1.f / (1.f + expf(-(a0 + __ldg(&b_bb[0]))));
        out[b * 4 + 1] = 1.f / (1.f + expf(-(a1 + __ldg(&b_bb[1]))));
        out[b * 4 + 2] = 1.f / (1.f + expf(-(a2 + __ldg(&b_bb[2]))));
        out[b * 4 + 3] = 1.f / (1.f + expf(-(a3 + __ldg(&b_bb[3]))));
    }
}

extern "C" void kernel_launch(void* const* d_in, const int* in_sizes, int n_in,
                              void* d_out, int out_size) {
    const float* x0    = (const float*)d_in[0];
    const float* flow  = (const float*)d_in[1];
    const float* h     = (const float*)d_in[2];
    const float* W_in  = (const float*)d_in[3];
    const float* W_x   = (const float*)d_in[4];
    const float* W_dt  = (const float*)d_in[5];
    const float* b_dt  = (const float*)d_in[6];
    const float* A_log = (const float*)d_in[7];
    const float* Dv    = (const float*)d_in[8];
    const float* W1    = (const float*)d_in[9];
    const float* b1    = (const float*)d_in[10];
    const float* W2    = (const float*)d_in[11];
    const float* b2    = (const float*)d_in[12];
    const float* gamma = (const float*)d_in[13];
    const float* beta  = (const float*)d_in[14];
    const float* W_bb  = (const float*)d_in[15];
    const float* b_bb  = (const float*)d_in[16];

    float* out   = (float*)d_out;                 // (B, 4)
    float* h_new = out + (size_t)BTOT * 4;        // (B, 256, 16)

    const int GSMEM = 2 * 32768 + 128;
    cudaFuncSetAttribute(k_hgemm<256, 512, 0>,
                         cudaFuncAttributeMaxDynamicSharedMemorySize, GSMEM);
    cudaFuncSetAttribute(k_hgemm<256, 512, 1>,
                         cudaFuncAttributeMaxDynamicSharedMemorySize, GSMEM);
    cudaFuncSetAttribute(k_hgemm<512, 256, 2>,
                         cudaFuncAttributeMaxDynamicSharedMemorySize, GSMEM);
    const int PGRID = 296;   // 148 SMs x 2 CTAs

    static cudaStream_t s1 = nullptr;
    static cudaEvent_t evFork = nullptr, evJoin = nullptr;
    if (s1 == nullptr) {
        cudaStreamCreateWithFlags(&s1, cudaStreamNonBlocking);
        cudaEventCreateWithFlags(&evFork, cudaEventDisableTiming);
        cudaEventCreateWithFlags(&evJoin, cudaEventDisableTiming);
    }

    // shared weight prep (serial, ~15us)
    k_prep<<<16, 256>>>(A_log);
    k_packw<<<512, 256>>>(W_in, 256, 0);
    k_packw<<<512, 256>>>(W1, 256, 1);
    k_packw<<<512, 256>>>(W2, 512, 2);
    cudaEventRecord(evFork, 0);
    cudaStreamWaitEvent(s1, evFork, 0);

    // ---- half 0 on main stream ----
    k_embed<<<BHALF / 2, 256>>>(x0, 0);
    k_xdbl<<<dim3(BHALF / 16, 3), 256>>>(flow, W_x, W_dt, b_dt, 0);
    k_hgemm<256, 512, 0><<<PGRID, 256, GSMEM>>>((const float*)nullptr, 0);
    k_mamba<<<BHALF, 256>>>(h, Dv, h_new, 0);
    k_hgemm<256, 512, 1><<<PGRID, 256, GSMEM>>>(b1, 0);
    k_hgemm<512, 256, 2><<<PGRID, 256, GSMEM>>>(b2, 0);
    k_head<<<BHALF / 8, 256>>>(gamma, beta, W_bb, b_bb, out, 0);

    // ---- half 1 on side stream ----
    k_embed<<<BHALF / 2, 256, 0, s1>>>(x0, BHALF);
    k_xdbl<<<dim3(BHALF / 16, 3), 256, 0, s1>>>(flow, W_x, W_dt, b_dt, BHALF);
    k_hgemm<256, 512, 0><<<PGRID, 256, GSMEM, s1>>>((const float*)nullptr, BHALF);
    k_mamba<<<BHALF, 256, 0, s1>>>(h, Dv, h_new, BHALF);
    k_hgemm<256, 512, 1><<<PGRID, 256, GSMEM, s1>>>(b1, BHALF);
    k_hgemm<512, 256, 2><<<PGRID, 256, GSMEM, s1>>>(b2, BHALF);
    k_head<<<BHALF / 8, 256, 0, s1>>>(gamma, beta, W_bb, b_bb, out, BHALF);

    cudaEventRecord(evJoin, s1);
    cudaStreamWaitEvent(0, evJoin, 0);
}